// round 16
// baseline (speedup 1.0000x reference)
#include <cuda_runtime.h>
#include <cuda_bf16.h>
#include <cstdint>

// Problem constants
#define Tn  2
#define PHn 4
#define CHn 8
#define Hn  128
#define Wn  128
#define Kn  1024
#define Bn  8            // Tn*PHn
#define BCn 64           // Bn*CHn
#define HW  (Hn*Wn)      // 16384
#define NPIX (Bn*HW)     // 131072 complex per output

__device__ __forceinline__ float bfr(float x) {
    return __bfloat162float(__float2bfloat16(x));
}
__device__ __forceinline__ uint32_t packbf(float a, float b) {
    __nv_bfloat162 t = __floats2bfloat162_rn(a, b);
    return *reinterpret_cast<uint32_t*>(&t);
}

// mma.sync m16n8k16 row.col f32.bf16.bf16.f32 (base PTX, sm_80+; OK on sm_103)
__device__ __forceinline__ void mma_bf16(float* c, const uint32_t* a, const uint32_t* b) {
    asm volatile(
        "mma.sync.aligned.m16n8k16.row.col.f32.bf16.bf16.f32 "
        "{%0,%1,%2,%3}, {%4,%5,%6,%7}, {%8,%9}, {%0,%1,%2,%3};"
        : "+f"(c[0]), "+f"(c[1]), "+f"(c[2]), "+f"(c[3])
        : "r"(a[0]), "r"(a[1]), "r"(a[2]), "r"(a[3]), "r"(b[0]), "r"(b[1]));
}

// K-chunk: 16 real contraction indices -> 96 bf16 slots = 48 words, pitch 52.
#define KRC        16
#define KPITCH_W   52

// k_adj smem geometry (bytes)
#define ADJ_A_OFF  0
#define ADJ_A_SZ   (64*KPITCH_W*4)
#define ADJ_BRE_OFF (ADJ_A_OFF + ADJ_A_SZ)
#define ADJ_B_SZ   (128*KPITCH_W*4)
#define ADJ_BIM_OFF (ADJ_BRE_OFF + ADJ_B_SZ)
#define ADJ_SMEM   (ADJ_BIM_OFF + ADJ_B_SZ)   // 66560

// k_fwd smem geometry (bytes)
#define FWD_A_OFF  0
#define FWD_A_SZ   (128*KPITCH_W*4)           // 26624
#define FWD_BR_OFF (FWD_A_OFF + FWD_A_SZ)
#define FWD_B_SZ   (64*KPITCH_W*4)            // 13312
#define FWD_BI_OFF (FWD_BR_OFF + FWD_B_SZ)
#define FWD_EST_OFF (FWD_BI_OFF + FWD_B_SZ)   // 53248
#define FWD_SMEM   (FWD_EST_OFF + 2*128*8)    // 55296

// ---------------- scratch (static device globals; no runtime alloc) --------
__device__ float2 g_Ex[Bn*Kn*Hn];
__device__ float2 g_Ey[Bn*Kn*Wn];
__device__ uint32_t g_pAdjB[6][Bn*Kn*Wn];   // conj(Ey) slot planes (25 MB)
__device__ uint32_t g_pFwdA[3][Bn*Kn*Hn];   // Ex slot planes (12.6 MB)
__device__ float2 g_csmn[Tn*CHn*HW];
__device__ float2 g_S1[BCn*HW];
__device__ float2 g_estp[2*BCn*Kn];
__device__ float2 g_est[BCn*Kn];
__device__ float2 g_p0[Bn*HW];
__device__ float2 g_p1[Bn*HW];
__device__ float2 g_init[Bn*HW];

// ---------------- kernels --------------------------------------------------

__global__ void k_exp(const float* __restrict__ traj) {
    int bk = blockIdx.x;
    int b  = bk >> 10;
    int k  = bk & (Kn - 1);
    float tx = traj[(b*2 + 0)*Kn + k];
    float ty = traj[(b*2 + 1)*Kn + k];
    int h = threadIdx.x;
    float xs = (float)(h - Hn/2);
    float s, c;
    int idx = bk*Hn + h;
    sincosf(tx * xs, &s, &c);
    g_Ex[idx] = make_float2(c, -s);
    // fwd A slots (Ex non-conj): ar=c, ai=-s
    {
        float ar = c, ai = -s;
        float arh = bfr(ar), arl = ar - arh;
        float aih = bfr(ai), ail = ai - aih;
        g_pFwdA[0][idx] = packbf(arh, arh);
        g_pFwdA[1][idx] = packbf(arl, aih);
        g_pFwdA[2][idx] = packbf(aih, ail);
    }
    sincosf(ty * xs, &s, &c);
    g_Ey[idx] = make_float2(c, -s);
    // adjoint B slots (conj(Ey)): br=c, bi=s
    {
        float br = c, bi = s;
        float brh = bfr(br), brl = br - brh;
        float bih = bfr(bi), bil = bi - bih;
        g_pAdjB[0][idx] = packbf(brh, brl);
        g_pAdjB[1][idx] = packbf(brh, -bih);
        g_pAdjB[2][idx] = packbf(-bil, -bih);
        g_pAdjB[3][idx] = packbf(bih, bil);
        g_pAdjB[4][idx] = packbf(bih, brh);
        g_pAdjB[5][idx] = packbf(brl, brh);
    }
}

__global__ void k_csm(const float2* __restrict__ csm) {
    int i = blockIdx.x*blockDim.x + threadIdx.x;
    if (i >= Tn*CHn*HW) return;
    float2 v = csm[i];
    float inv = rsqrtf(v.x*v.x + v.y*v.y);
    g_csmn[i] = make_float2(v.x*inv, v.y*inv);
}

// ============ HMMA adjoint: S1 = sum_k (conj(Ex)*u)[k,h] * conj(Ey)[k,w] ====
__global__ void __launch_bounds__(256, 2) k_adj(const float2* __restrict__ uext, int use_est) {
    extern __shared__ __align__(16) char smem[];
    uint32_t* A32  = (uint32_t*)(smem + ADJ_A_OFF);
    uint32_t* BR32 = (uint32_t*)(smem + ADJ_BRE_OFF);
    uint32_t* BI32 = (uint32_t*)(smem + ADJ_BIM_OFF);

    int tid = threadIdx.x, lane = tid & 31, wid = tid >> 5;
    int h0 = blockIdx.x * 64;
    int bc = blockIdx.y, b = bc >> 3;
    const float2* __restrict__ Ex = g_Ex + b*(Kn*Hn);
    const float2* __restrict__ ub = (use_est ? g_est : uext) + bc*Kn;
    const int bbase = b*(Kn*Wn);

    int warpM = wid >> 2;
    int warpN = wid & 3;

    float acc[2][4][2][4];
    #pragma unroll
    for (int mt = 0; mt < 2; mt++)
        #pragma unroll
        for (int nt = 0; nt < 4; nt++)
            #pragma unroll
            for (int pl = 0; pl < 2; pl++)
                #pragma unroll
                for (int q = 0; q < 4; q++) acc[mt][nt][pl][q] = 0.f;

    for (int k0 = 0; k0 < Kn; k0 += KRC) {
        // ---- A: (conj(Ex)*u), 16 kr x 64 h — split in-kernel
        #pragma unroll
        for (int l = 0; l < 4; l++) {
            int idx = tid + l*256;
            int kr = idx >> 6, m = idx & 63;
            float2 ex = Ex[(k0 + kr)*Hn + h0 + m];
            float2 uk = ub[k0 + kr];
            float ax = ex.x, ay = -ex.y;
            float ar = ax*uk.x - ay*uk.y;
            float ai = ax*uk.y + ay*uk.x;
            float arh = bfr(ar), arl = ar - arh;
            float aih = bfr(ai), ail = ai - aih;
            uint32_t* dst = A32 + m*KPITCH_W + 3*kr;
            dst[0] = packbf(arh, arh);
            dst[1] = packbf(arl, aih);
            dst[2] = packbf(aih, ail);
        }
        // ---- B: precomputed conj(Ey) slot planes — pure copy
        #pragma unroll
        for (int l = 0; l < 8; l++) {
            int idx = tid + l*256;
            int kr = idx >> 7, w = idx & 127;
            int gi = bbase + (k0 + kr)*Wn + w;
            uint32_t* dr = BR32 + w*KPITCH_W + 3*kr;
            dr[0] = g_pAdjB[0][gi];
            dr[1] = g_pAdjB[1][gi];
            dr[2] = g_pAdjB[2][gi];
            uint32_t* di = BI32 + w*KPITCH_W + 3*kr;
            di[0] = g_pAdjB[3][gi];
            di[1] = g_pAdjB[4][gi];
            di[2] = g_pAdjB[5][gi];
        }
        __syncthreads();

        #pragma unroll
        for (int ks = 0; ks < 6; ks++) {
            int cw = ks*8 + (lane & 3);
            uint32_t afr[2][4];
            #pragma unroll
            for (int mt = 0; mt < 2; mt++) {
                int r0 = warpM*32 + mt*16 + (lane >> 2);
                afr[mt][0] = A32[r0*KPITCH_W + cw];
                afr[mt][1] = A32[(r0+8)*KPITCH_W + cw];
                afr[mt][2] = A32[r0*KPITCH_W + cw + 4];
                afr[mt][3] = A32[(r0+8)*KPITCH_W + cw + 4];
            }
            #pragma unroll
            for (int nt = 0; nt < 4; nt++) {
                int nn = warpN*32 + nt*8 + (lane >> 2);
                uint32_t bre[2], bim[2];
                bre[0] = BR32[nn*KPITCH_W + cw];
                bre[1] = BR32[nn*KPITCH_W + cw + 4];
                bim[0] = BI32[nn*KPITCH_W + cw];
                bim[1] = BI32[nn*KPITCH_W + cw + 4];
                #pragma unroll
                for (int mt = 0; mt < 2; mt++) {
                    mma_bf16(acc[mt][nt][0], afr[mt], bre);
                    mma_bf16(acc[mt][nt][1], afr[mt], bim);
                }
            }
        }
        __syncthreads();
    }

    float* __restrict__ of = (float*)(g_S1 + bc*HW);
    int r = lane >> 2, q = (lane & 3)*2;
    #pragma unroll
    for (int mt = 0; mt < 2; mt++)
        #pragma unroll
        for (int nt = 0; nt < 4; nt++) {
            int h = h0 + warpM*32 + mt*16 + r;
            int w = warpN*32 + nt*8 + q;
            #pragma unroll
            for (int pl = 0; pl < 2; pl++) {
                const float* c = acc[mt][nt][pl];
                of[(h*Wn + w)*2 + pl]       = c[0];
                of[(h*Wn + w + 1)*2 + pl]   = c[1];
                of[((h+8)*Wn + w)*2 + pl]   = c[2];
                of[((h+8)*Wn + w + 1)*2+pl] = c[3];
            }
        }
}

__global__ void k_combine_init() {
    int i = blockIdx.x*blockDim.x + threadIdx.x;
    if (i >= Bn*HW) return;
    int b = i >> 14, hw = i & (HW - 1), t = b >> 2;
    float2 s = make_float2(0.f, 0.f);
    #pragma unroll
    for (int c = 0; c < CHn; c++) {
        float2 im = g_S1[(b*CHn + c)*HW + hw];
        float2 cs = g_csmn[(t*CHn + c)*HW + hw];
        s.x += cs.x*im.x + cs.y*im.y;
        s.y += cs.x*im.y - cs.y*im.x;
    }
    s.x *= 0.2f; s.y *= 0.2f;
    g_p0[i] = s;
    g_init[i] = s;
}

// ============ HMMA forward + fused est ============
__global__ void __launch_bounds__(256, 2) k_fwd(int psel) {
    extern __shared__ __align__(16) char smem[];
    uint32_t* A32  = (uint32_t*)(smem + FWD_A_OFF);
    uint32_t* BR32 = (uint32_t*)(smem + FWD_BR_OFF);
    uint32_t* BI32 = (uint32_t*)(smem + FWD_BI_OFF);
    float2*  sEst  = (float2*)(smem + FWD_EST_OFF);

    const float2* __restrict__ p = psel ? g_p1 : g_p0;
    int tid = threadIdx.x, lane = tid & 31, wid = tid >> 5;
    int k0 = blockIdx.x * 128;
    int wtile = blockIdx.y, w0 = wtile * 64;
    int bc = blockIdx.z, b = bc >> 3, c = bc & 7, t = b >> 2;
    const float2* __restrict__ Eyb = g_Ey + b*(Kn*Wn);
    const float2* __restrict__ pb = p + b*HW;
    const float2* __restrict__ cs = g_csmn + (t*CHn + c)*HW;
    const int abase = b*(Kn*Hn);

    int warpM = wid >> 1;
    int warpN = wid & 1;

    float acc[2][4][2][4];
    #pragma unroll
    for (int mt = 0; mt < 2; mt++)
        #pragma unroll
        for (int nt = 0; nt < 4; nt++)
            #pragma unroll
            for (int pl = 0; pl < 2; pl++)
                #pragma unroll
                for (int q = 0; q < 4; q++) acc[mt][nt][pl][q] = 0.f;

    for (int hh0 = 0; hh0 < Hn; hh0 += KRC) {
        // ---- A: precomputed Ex slot planes — pure copy
        #pragma unroll
        for (int l = 0; l < 8; l++) {
            int idx = tid + l*256;
            int hr = idx & 15, m = idx >> 4;
            int gi = abase + (k0 + m)*Hn + hh0 + hr;
            uint32_t* dst = A32 + m*KPITCH_W + 3*hr;
            dst[0] = g_pFwdA[0][gi];
            dst[1] = g_pFwdA[1][gi];
            dst[2] = g_pFwdA[2][gi];
        }
        // ---- B: m = p*csm, split in-kernel
        #pragma unroll
        for (int l = 0; l < 4; l++) {
            int idx = tid + l*256;
            int hr = idx >> 6, w = idx & 63;
            float2 pv = pb[(hh0 + hr)*Wn + w0 + w];
            float2 cv = cs[(hh0 + hr)*Wn + w0 + w];
            float br = pv.x*cv.x - pv.y*cv.y;
            float bi = pv.x*cv.y + pv.y*cv.x;
            float brh = bfr(br), brl = br - brh;
            float bih = bfr(bi), bil = bi - bih;
            uint32_t* dr = BR32 + w*KPITCH_W + 3*hr;
            dr[0] = packbf(brh, brl);
            dr[1] = packbf(brh, -bih);
            dr[2] = packbf(-bil, -bih);
            uint32_t* di = BI32 + w*KPITCH_W + 3*hr;
            di[0] = packbf(bih, bil);
            di[1] = packbf(bih, brh);
            di[2] = packbf(brl, brh);
        }
        __syncthreads();

        #pragma unroll
        for (int ks = 0; ks < 6; ks++) {
            int cw = ks*8 + (lane & 3);
            uint32_t afr[2][4];
            #pragma unroll
            for (int mt = 0; mt < 2; mt++) {
                int r0 = warpM*32 + mt*16 + (lane >> 2);
                afr[mt][0] = A32[r0*KPITCH_W + cw];
                afr[mt][1] = A32[(r0+8)*KPITCH_W + cw];
                afr[mt][2] = A32[r0*KPITCH_W + cw + 4];
                afr[mt][3] = A32[(r0+8)*KPITCH_W + cw + 4];
            }
            #pragma unroll
            for (int nt = 0; nt < 4; nt++) {
                int nn = warpN*32 + nt*8 + (lane >> 2);
                uint32_t bre[2], bim[2];
                bre[0] = BR32[nn*KPITCH_W + cw];
                bre[1] = BR32[nn*KPITCH_W + cw + 4];
                bim[0] = BI32[nn*KPITCH_W + cw];
                bim[1] = BI32[nn*KPITCH_W + cw + 4];
                #pragma unroll
                for (int mt = 0; mt < 2; mt++) {
                    mma_bf16(acc[mt][nt][0], afr[mt], bre);
                    mma_bf16(acc[mt][nt][1], afr[mt], bim);
                }
            }
        }
        __syncthreads();
    }

    // ---- fused est epilogue
    int r = lane >> 2;
    #pragma unroll
    for (int mt = 0; mt < 2; mt++) {
        int row0 = warpM*32 + mt*16 + r;
        float sx0 = 0.f, sy0 = 0.f, sx1 = 0.f, sy1 = 0.f;
        #pragma unroll
        for (int nt = 0; nt < 4; nt++) {
            int wloc = warpN*32 + nt*8 + (lane & 3)*2;
            const float* c0 = acc[mt][nt][0];
            const float* c1 = acc[mt][nt][1];
            float2 e0 = Eyb[(k0 + row0)*Wn + w0 + wloc];
            float2 e1 = Eyb[(k0 + row0)*Wn + w0 + wloc + 1];
            sx0 += c0[0]*e0.x - c1[0]*e0.y + c0[1]*e1.x - c1[1]*e1.y;
            sy0 += c0[0]*e0.y + c1[0]*e0.x + c0[1]*e1.y + c1[1]*e1.x;
            float2 e2 = Eyb[(k0 + row0 + 8)*Wn + w0 + wloc];
            float2 e3 = Eyb[(k0 + row0 + 8)*Wn + w0 + wloc + 1];
            sx1 += c0[2]*e2.x - c1[2]*e2.y + c0[3]*e3.x - c1[3]*e3.y;
            sy1 += c0[2]*e2.y + c1[2]*e2.x + c0[3]*e3.y + c1[3]*e3.x;
        }
        #pragma unroll
        for (int m = 1; m <= 2; m <<= 1) {
            sx0 += __shfl_xor_sync(0xffffffffu, sx0, m);
            sy0 += __shfl_xor_sync(0xffffffffu, sy0, m);
            sx1 += __shfl_xor_sync(0xffffffffu, sx1, m);
            sy1 += __shfl_xor_sync(0xffffffffu, sy1, m);
        }
        if ((lane & 3) == 0) {
            sEst[warpN*128 + row0]     = make_float2(sx0, sy0);
            sEst[warpN*128 + row0 + 8] = make_float2(sx1, sy1);
        }
    }
    __syncthreads();
    if (tid < 128) {
        float2 a = sEst[tid], bpart = sEst[128 + tid];
        g_estp[(wtile*BCn + bc)*Kn + k0 + tid] =
            make_float2(a.x + bpart.x, a.y + bpart.y);
    }
}

__global__ void k_est2(const float2* __restrict__ ksp) {
    int i = blockIdx.x*blockDim.x + threadIdx.x;
    if (i >= BCn*Kn) return;
    float2 a = g_estp[i];
    float2 bb = g_estp[BCn*Kn + i];
    float2 kv = ksp[i];
    const float inv = 1.0f / 131072.0f;
    g_est[i] = make_float2((a.x + bb.x - kv.x)*inv, (a.y + bb.y - kv.y)*inv);
}

__global__ void k_update(int psel) {
    int i = blockIdx.x*blockDim.x + threadIdx.x;
    if (i >= Bn*HW) return;
    const float2* __restrict__ pin = psel ? g_p1 : g_p0;
    float2* __restrict__ pout = psel ? g_p0 : g_p1;
    int b = i >> 14, hw = i & (HW - 1), t = b >> 2, ph = b & 3;

    float gx = 0.f, gy = 0.f;
    #pragma unroll
    for (int c = 0; c < CHn; c++) {
        float2 im = g_S1[(b*CHn + c)*HW + hw];
        float2 cs = g_csmn[(t*CHn + c)*HW + hw];
        gx += cs.x*im.x + cs.y*im.y;
        gy += cs.x*im.y - cs.y*im.x;
    }

    float2 pv = pin[i];
    const float ctc = 0.01f / 65536.0f;
    const float ctr = 0.01f / 98304.0f;

    if (t + 1 < Tn) {
        float2 n = pin[i + PHn*HW];
        float dx = n.x - pv.x, dy = n.y - pv.y;
        float inv = rsqrtf(dx*dx + dy*dy);
        gx -= ctc * dx * inv; gy -= ctc * dy * inv;
    }
    if (t >= 1) {
        float2 n = pin[i - PHn*HW];
        float dx = pv.x - n.x, dy = pv.y - n.y;
        float inv = rsqrtf(dx*dx + dy*dy);
        gx += ctc * dx * inv; gy += ctc * dy * inv;
    }
    if (ph + 1 < PHn) {
        float2 n = pin[i + HW];
        float dx = n.x - pv.x, dy = n.y - pv.y;
        float inv = rsqrtf(dx*dx + dy*dy);
        gx -= ctr * dx * inv; gy -= ctr * dy * inv;
    }
    if (ph >= 1) {
        float2 n = pin[i - HW];
        float dx = pv.x - n.x, dy = pv.y - n.y;
        float inv = rsqrtf(dx*dx + dy*dy);
        gx += ctr * dx * inv; gy += ctr * dy * inv;
    }

    pout[i] = make_float2(pv.x - 0.5f*gx, pv.y - 0.5f*gy);
}

// FINAL node. Decoded harness geometry (DO NOT CHANGE):
//   output0 window floats [0, N): params.real
//   output1 window floats [N,2N): image_init.real
__global__ void k_writeout_all(float* __restrict__ out) {
    int i = blockIdx.x*blockDim.x + threadIdx.x;
    if (i >= Bn*HW) return;
    float2 p = g_p0[i];
    float2 v = g_init[i];
    out[i]          = p.x;
    out[i +   NPIX] = v.x;
    out[i + 2*NPIX] = p.y;
    out[i + 3*NPIX] = v.y;
}

// ---------------- host launcher --------------------------------------------
extern "C" void kernel_launch(void* const* d_in, const int* in_sizes, int n_in,
                              void* d_out, int out_size) {
    const float2* kd  = 0;
    const float2* kdc = 0;
    const float*  traj = 0;
    const float2* csm = 0;
    int n131 = 0;
    for (int i = 0; i < n_in; i++) {
        if (in_sizes[i] == 16384) {
            traj = (const float*)d_in[i];
        } else if (in_sizes[i] == 524288) {
            csm = (const float2*)d_in[i];
        } else if (in_sizes[i] == 131072) {
            if (n131 == 0) kd  = (const float2*)d_in[i];
            else           kdc = (const float2*)d_in[i];
            n131++;
        }
    }
    float* out = (float*)d_out;

    cudaFuncSetAttribute(k_adj, cudaFuncAttributeMaxDynamicSharedMemorySize, ADJ_SMEM);
    cudaFuncSetAttribute(k_fwd, cudaFuncAttributeMaxDynamicSharedMemorySize, FWD_SMEM);

    k_exp<<<Bn*Kn, Hn>>>(traj);
    k_csm<<<(Tn*CHn*HW + 255)/256, 256>>>(csm);

    k_adj<<<dim3(2, BCn), 256, ADJ_SMEM>>>(kdc, 0);
    k_combine_init<<<(Bn*HW + 255)/256, 256>>>();

    for (int step = 0; step < 2; step++) {
        int psel = step & 1;
        k_fwd<<<dim3(Kn/128, 2, BCn), 256, FWD_SMEM>>>(psel);
        k_est2<<<(BCn*Kn + 255)/256, 256>>>(kd);
        k_adj<<<dim3(2, BCn), 256, ADJ_SMEM>>>(nullptr, 1);
        k_update<<<(Bn*HW + 255)/256, 256>>>(psel);
    }

    k_writeout_all<<<(Bn*HW + 255)/256, 256>>>(out);
}

// round 17
// speedup vs baseline: 1.1075x; 1.1075x over previous
#include <cuda_runtime.h>
#include <cuda_bf16.h>
#include <cstdint>

// Problem constants
#define Tn  2
#define PHn 4
#define CHn 8
#define Hn  128
#define Wn  128
#define Kn  1024
#define Bn  8            // Tn*PHn
#define BCn 64           // Bn*CHn
#define HW  (Hn*Wn)      // 16384
#define NPIX (Bn*HW)     // 131072 complex per output

__device__ __forceinline__ float bfr(float x) {
    return __bfloat162float(__float2bfloat16(x));
}
__device__ __forceinline__ uint32_t packbf(float a, float b) {
    __nv_bfloat162 t = __floats2bfloat162_rn(a, b);
    return *reinterpret_cast<uint32_t*>(&t);
}

// mma.sync m16n8k16 row.col f32.bf16.bf16.f32 (base PTX, sm_80+; OK on sm_103)
__device__ __forceinline__ void mma_bf16(float* c, const uint32_t* a, const uint32_t* b) {
    asm volatile(
        "mma.sync.aligned.m16n8k16.row.col.f32.bf16.bf16.f32 "
        "{%0,%1,%2,%3}, {%4,%5,%6,%7}, {%8,%9}, {%0,%1,%2,%3};"
        : "+f"(c[0]), "+f"(c[1]), "+f"(c[2]), "+f"(c[3])
        : "r"(a[0]), "r"(a[1]), "r"(a[2]), "r"(a[3]), "r"(b[0]), "r"(b[1]));
}

// K-chunk: 16 real contraction indices -> 96 bf16 slots = 48 words, pitch 52.
#define KRC        16
#define KPITCH_W   52

// k_adj smem geometry (bytes): 64h x 64w tile
#define ADJ_A_OFF  0
#define ADJ_A_SZ   (64*KPITCH_W*4)            // 13312
#define ADJ_BRE_OFF (ADJ_A_OFF + ADJ_A_SZ)
#define ADJ_B_SZ   (64*KPITCH_W*4)            // 13312
#define ADJ_BIM_OFF (ADJ_BRE_OFF + ADJ_B_SZ)
#define ADJ_SMEM   (ADJ_BIM_OFF + ADJ_B_SZ)   // 39936

// k_fwd smem geometry (bytes)
#define FWD_A_OFF  0
#define FWD_A_SZ   (128*KPITCH_W*4)           // 26624
#define FWD_BR_OFF (FWD_A_OFF + FWD_A_SZ)
#define FWD_B_SZ   (64*KPITCH_W*4)            // 13312
#define FWD_BI_OFF (FWD_BR_OFF + FWD_B_SZ)
#define FWD_EST_OFF (FWD_BI_OFF + FWD_B_SZ)   // 53248
#define FWD_SMEM   (FWD_EST_OFF + 2*128*8)    // 55296

// ---------------- scratch (static device globals; no runtime alloc) --------
__device__ float2 g_Ex[Bn*Kn*Hn];
__device__ float2 g_Ey[Bn*Kn*Wn];
__device__ float2 g_csmn[Tn*CHn*HW];
__device__ float2 g_S1[BCn*HW];
__device__ float2 g_estp[2*BCn*Kn];
__device__ float2 g_est[BCn*Kn];
__device__ float2 g_p0[Bn*HW];
__device__ float2 g_p1[Bn*HW];
__device__ float2 g_init[Bn*HW];

// ---------------- kernels --------------------------------------------------

__global__ void k_exp(const float* __restrict__ traj) {
    int bk = blockIdx.x;
    int b  = bk >> 10;
    int k  = bk & (Kn - 1);
    float tx = traj[(b*2 + 0)*Kn + k];
    float ty = traj[(b*2 + 1)*Kn + k];
    int h = threadIdx.x;
    float xs = (float)(h - Hn/2);
    float s, c;
    sincosf(tx * xs, &s, &c);
    g_Ex[bk*Hn + h] = make_float2(c, -s);
    sincosf(ty * xs, &s, &c);
    g_Ey[bk*Wn + h] = make_float2(c, -s);
}

__global__ void k_csm(const float2* __restrict__ csm) {
    int i = blockIdx.x*blockDim.x + threadIdx.x;
    if (i >= Tn*CHn*HW) return;
    float2 v = csm[i];
    float inv = rsqrtf(v.x*v.x + v.y*v.y);
    g_csmn[i] = make_float2(v.x*inv, v.y*inv);
}

// ===== HMMA adjoint, 64h x 64w tiles (256 blocks), occ 2 =====
// S1[bc,h,w] = sum_k conj(Ex[b,k,h]) * ( u[bc,k] * conj(Ey[b,k,w]) )
__global__ void __launch_bounds__(256, 2) k_adj(const float2* __restrict__ uext, int use_est) {
    extern __shared__ __align__(16) char smem[];
    uint32_t* A32  = (uint32_t*)(smem + ADJ_A_OFF);
    uint32_t* BR32 = (uint32_t*)(smem + ADJ_BRE_OFF);
    uint32_t* BI32 = (uint32_t*)(smem + ADJ_BIM_OFF);

    int tid = threadIdx.x, lane = tid & 31, wid = tid >> 5;
    int h0 = blockIdx.x * 64;
    int w0 = blockIdx.y * 64;
    int bc = blockIdx.z, b = bc >> 3;
    const float2* __restrict__ Ex = g_Ex + b*(Kn*Hn);
    const float2* __restrict__ Ey = g_Ey + b*(Kn*Wn);
    const float2* __restrict__ ub = (use_est ? g_est : uext) + bc*Kn;

    int warpM = wid >> 2;     // 0..1 -> 32 h rows each
    int warpN = wid & 3;      // 0..3 -> 16 w cols each

    float acc[2][2][2][4];    // [mt][nt][plane][q]
    #pragma unroll
    for (int mt = 0; mt < 2; mt++)
        #pragma unroll
        for (int nt = 0; nt < 2; nt++)
            #pragma unroll
            for (int pl = 0; pl < 2; pl++)
                #pragma unroll
                for (int q = 0; q < 4; q++) acc[mt][nt][pl][q] = 0.f;

    for (int k0 = 0; k0 < Kn; k0 += KRC) {
        // ---- A: conj(Ex), 16 kr x 64 h
        #pragma unroll
        for (int l = 0; l < 4; l++) {
            int idx = tid + l*256;
            int kr = idx >> 6, m = idx & 63;
            float2 ex = Ex[(k0 + kr)*Hn + h0 + m];
            float ar = ex.x, ai = -ex.y;
            float arh = bfr(ar), arl = ar - arh;
            float aih = bfr(ai), ail = ai - aih;
            uint32_t* dst = A32 + m*KPITCH_W + 3*kr;
            dst[0] = packbf(arh, arh);
            dst[1] = packbf(arl, aih);
            dst[2] = packbf(aih, ail);
        }
        // ---- B: v = u*conj(Ey), 16 kr x 64 w
        #pragma unroll
        for (int l = 0; l < 4; l++) {
            int idx = tid + l*256;
            int kr = idx >> 6, w = idx & 63;
            float2 uk = ub[k0 + kr];
            float2 ey = Ey[(k0 + kr)*Wn + w0 + w];
            float vr = uk.x*ey.x + uk.y*ey.y;
            float vi = uk.y*ey.x - uk.x*ey.y;
            float brh = bfr(vr), brl = vr - brh;
            float bih = bfr(vi), bil = vi - bih;
            uint32_t* dr = BR32 + w*KPITCH_W + 3*kr;
            dr[0] = packbf(brh, brl);
            dr[1] = packbf(brh, -bih);
            dr[2] = packbf(-bil, -bih);
            uint32_t* di = BI32 + w*KPITCH_W + 3*kr;
            di[0] = packbf(bih, bil);
            di[1] = packbf(bih, brh);
            di[2] = packbf(brl, brh);
        }
        __syncthreads();

        #pragma unroll
        for (int ks = 0; ks < 6; ks++) {
            int cw = ks*8 + (lane & 3);
            uint32_t afr[2][4];
            #pragma unroll
            for (int mt = 0; mt < 2; mt++) {
                int r0 = warpM*32 + mt*16 + (lane >> 2);
                afr[mt][0] = A32[r0*KPITCH_W + cw];
                afr[mt][1] = A32[(r0+8)*KPITCH_W + cw];
                afr[mt][2] = A32[r0*KPITCH_W + cw + 4];
                afr[mt][3] = A32[(r0+8)*KPITCH_W + cw + 4];
            }
            #pragma unroll
            for (int nt = 0; nt < 2; nt++) {
                int nn = warpN*16 + nt*8 + (lane >> 2);
                uint32_t bre[2], bim[2];
                bre[0] = BR32[nn*KPITCH_W + cw];
                bre[1] = BR32[nn*KPITCH_W + cw + 4];
                bim[0] = BI32[nn*KPITCH_W + cw];
                bim[1] = BI32[nn*KPITCH_W + cw + 4];
                #pragma unroll
                for (int mt = 0; mt < 2; mt++) {
                    mma_bf16(acc[mt][nt][0], afr[mt], bre);
                    mma_bf16(acc[mt][nt][1], afr[mt], bim);
                }
            }
        }
        __syncthreads();
    }

    float* __restrict__ of = (float*)(g_S1 + bc*HW);
    int r = lane >> 2, q = (lane & 3)*2;
    #pragma unroll
    for (int mt = 0; mt < 2; mt++)
        #pragma unroll
        for (int nt = 0; nt < 2; nt++) {
            int h = h0 + warpM*32 + mt*16 + r;
            int w = w0 + warpN*16 + nt*8 + q;
            #pragma unroll
            for (int pl = 0; pl < 2; pl++) {
                const float* c = acc[mt][nt][pl];
                of[(h*Wn + w)*2 + pl]       = c[0];
                of[(h*Wn + w + 1)*2 + pl]   = c[1];
                of[((h+8)*Wn + w)*2 + pl]   = c[2];
                of[((h+8)*Wn + w + 1)*2+pl] = c[3];
            }
        }
}

__global__ void k_combine_init() {
    int i = blockIdx.x*blockDim.x + threadIdx.x;
    if (i >= Bn*HW) return;
    int b = i >> 14, hw = i & (HW - 1), t = b >> 2;
    float2 s = make_float2(0.f, 0.f);
    #pragma unroll
    for (int c = 0; c < CHn; c++) {
        float2 im = g_S1[(b*CHn + c)*HW + hw];
        float2 cs = g_csmn[(t*CHn + c)*HW + hw];
        s.x += cs.x*im.x + cs.y*im.y;
        s.y += cs.x*im.y - cs.y*im.x;
    }
    s.x *= 0.2f; s.y *= 0.2f;
    g_p0[i] = s;
    g_init[i] = s;
}

// ============ HMMA forward + fused est (R15 passing version) ============
__global__ void __launch_bounds__(256, 2) k_fwd(int psel) {
    extern __shared__ __align__(16) char smem[];
    uint32_t* A32  = (uint32_t*)(smem + FWD_A_OFF);
    uint32_t* BR32 = (uint32_t*)(smem + FWD_BR_OFF);
    uint32_t* BI32 = (uint32_t*)(smem + FWD_BI_OFF);
    float2*  sEst  = (float2*)(smem + FWD_EST_OFF);

    const float2* __restrict__ p = psel ? g_p1 : g_p0;
    int tid = threadIdx.x, lane = tid & 31, wid = tid >> 5;
    int k0 = blockIdx.x * 128;
    int wtile = blockIdx.y, w0 = wtile * 64;
    int bc = blockIdx.z, b = bc >> 3, c = bc & 7, t = b >> 2;
    const float2* __restrict__ Ex = g_Ex + b*(Kn*Hn);
    const float2* __restrict__ Eyb = g_Ey + b*(Kn*Wn);
    const float2* __restrict__ pb = p + b*HW;
    const float2* __restrict__ cs = g_csmn + (t*CHn + c)*HW;

    int warpM = wid >> 1;
    int warpN = wid & 1;

    float acc[2][4][2][4];
    #pragma unroll
    for (int mt = 0; mt < 2; mt++)
        #pragma unroll
        for (int nt = 0; nt < 4; nt++)
            #pragma unroll
            for (int pl = 0; pl < 2; pl++)
                #pragma unroll
                for (int q = 0; q < 4; q++) acc[mt][nt][pl][q] = 0.f;

    for (int hh0 = 0; hh0 < Hn; hh0 += KRC) {
        #pragma unroll
        for (int l = 0; l < 8; l++) {
            int idx = tid + l*256;
            int hr = idx & 15, m = idx >> 4;
            float2 ex = Ex[(k0 + m)*Hn + hh0 + hr];
            float ar = ex.x, ai = ex.y;
            float arh = bfr(ar), arl = ar - arh;
            float aih = bfr(ai), ail = ai - aih;
            uint32_t* dst = A32 + m*KPITCH_W + 3*hr;
            dst[0] = packbf(arh, arh);
            dst[1] = packbf(arl, aih);
            dst[2] = packbf(aih, ail);
        }
        #pragma unroll
        for (int l = 0; l < 4; l++) {
            int idx = tid + l*256;
            int hr = idx >> 6, w = idx & 63;
            float2 pv = pb[(hh0 + hr)*Wn + w0 + w];
            float2 cv = cs[(hh0 + hr)*Wn + w0 + w];
            float br = pv.x*cv.x - pv.y*cv.y;
            float bi = pv.x*cv.y + pv.y*cv.x;
            float brh = bfr(br), brl = br - brh;
            float bih = bfr(bi), bil = bi - bih;
            uint32_t* dr = BR32 + w*KPITCH_W + 3*hr;
            dr[0] = packbf(brh, brl);
            dr[1] = packbf(brh, -bih);
            dr[2] = packbf(-bil, -bih);
            uint32_t* di = BI32 + w*KPITCH_W + 3*hr;
            di[0] = packbf(bih, bil);
            di[1] = packbf(bih, brh);
            di[2] = packbf(brl, brh);
        }
        __syncthreads();

        #pragma unroll
        for (int ks = 0; ks < 6; ks++) {
            int cw = ks*8 + (lane & 3);
            uint32_t afr[2][4];
            #pragma unroll
            for (int mt = 0; mt < 2; mt++) {
                int r0 = warpM*32 + mt*16 + (lane >> 2);
                afr[mt][0] = A32[r0*KPITCH_W + cw];
                afr[mt][1] = A32[(r0+8)*KPITCH_W + cw];
                afr[mt][2] = A32[r0*KPITCH_W + cw + 4];
                afr[mt][3] = A32[(r0+8)*KPITCH_W + cw + 4];
            }
            #pragma unroll
            for (int nt = 0; nt < 4; nt++) {
                int nn = warpN*32 + nt*8 + (lane >> 2);
                uint32_t bre[2], bim[2];
                bre[0] = BR32[nn*KPITCH_W + cw];
                bre[1] = BR32[nn*KPITCH_W + cw + 4];
                bim[0] = BI32[nn*KPITCH_W + cw];
                bim[1] = BI32[nn*KPITCH_W + cw + 4];
                #pragma unroll
                for (int mt = 0; mt < 2; mt++) {
                    mma_bf16(acc[mt][nt][0], afr[mt], bre);
                    mma_bf16(acc[mt][nt][1], afr[mt], bim);
                }
            }
        }
        __syncthreads();
    }

    int r = lane >> 2;
    #pragma unroll
    for (int mt = 0; mt < 2; mt++) {
        int row0 = warpM*32 + mt*16 + r;
        float sx0 = 0.f, sy0 = 0.f, sx1 = 0.f, sy1 = 0.f;
        #pragma unroll
        for (int nt = 0; nt < 4; nt++) {
            int wloc = warpN*32 + nt*8 + (lane & 3)*2;
            const float* c0 = acc[mt][nt][0];
            const float* c1 = acc[mt][nt][1];
            float2 e0 = Eyb[(k0 + row0)*Wn + w0 + wloc];
            float2 e1 = Eyb[(k0 + row0)*Wn + w0 + wloc + 1];
            sx0 += c0[0]*e0.x - c1[0]*e0.y + c0[1]*e1.x - c1[1]*e1.y;
            sy0 += c0[0]*e0.y + c1[0]*e0.x + c0[1]*e1.y + c1[1]*e1.x;
            float2 e2 = Eyb[(k0 + row0 + 8)*Wn + w0 + wloc];
            float2 e3 = Eyb[(k0 + row0 + 8)*Wn + w0 + wloc + 1];
            sx1 += c0[2]*e2.x - c1[2]*e2.y + c0[3]*e3.x - c1[3]*e3.y;
            sy1 += c0[2]*e2.y + c1[2]*e2.x + c0[3]*e3.y + c1[3]*e3.x;
        }
        #pragma unroll
        for (int m = 1; m <= 2; m <<= 1) {
            sx0 += __shfl_xor_sync(0xffffffffu, sx0, m);
            sy0 += __shfl_xor_sync(0xffffffffu, sy0, m);
            sx1 += __shfl_xor_sync(0xffffffffu, sx1, m);
            sy1 += __shfl_xor_sync(0xffffffffu, sy1, m);
        }
        if ((lane & 3) == 0) {
            sEst[warpN*128 + row0]     = make_float2(sx0, sy0);
            sEst[warpN*128 + row0 + 8] = make_float2(sx1, sy1);
        }
    }
    __syncthreads();
    if (tid < 128) {
        float2 a = sEst[tid], bpart = sEst[128 + tid];
        g_estp[(wtile*BCn + bc)*Kn + k0 + tid] =
            make_float2(a.x + bpart.x, a.y + bpart.y);
    }
}

__global__ void k_est2(const float2* __restrict__ ksp) {
    int i = blockIdx.x*blockDim.x + threadIdx.x;
    if (i >= BCn*Kn) return;
    float2 a = g_estp[i];
    float2 bb = g_estp[BCn*Kn + i];
    float2 kv = ksp[i];
    const float inv = 1.0f / 131072.0f;
    g_est[i] = make_float2((a.x + bb.x - kv.x)*inv, (a.y + bb.y - kv.y)*inv);
}

__global__ void k_update(int psel) {
    int i = blockIdx.x*blockDim.x + threadIdx.x;
    if (i >= Bn*HW) return;
    const float2* __restrict__ pin = psel ? g_p1 : g_p0;
    float2* __restrict__ pout = psel ? g_p0 : g_p1;
    int b = i >> 14, hw = i & (HW - 1), t = b >> 2, ph = b & 3;

    float gx = 0.f, gy = 0.f;
    #pragma unroll
    for (int c = 0; c < CHn; c++) {
        float2 im = g_S1[(b*CHn + c)*HW + hw];
        float2 cs = g_csmn[(t*CHn + c)*HW + hw];
        gx += cs.x*im.x + cs.y*im.y;
        gy += cs.x*im.y - cs.y*im.x;
    }

    float2 pv = pin[i];
    const float ctc = 0.01f / 65536.0f;
    const float ctr = 0.01f / 98304.0f;

    if (t + 1 < Tn) {
        float2 n = pin[i + PHn*HW];
        float dx = n.x - pv.x, dy = n.y - pv.y;
        float inv = rsqrtf(dx*dx + dy*dy);
        gx -= ctc * dx * inv; gy -= ctc * dy * inv;
    }
    if (t >= 1) {
        float2 n = pin[i - PHn*HW];
        float dx = pv.x - n.x, dy = pv.y - n.y;
        float inv = rsqrtf(dx*dx + dy*dy);
        gx += ctc * dx * inv; gy += ctc * dy * inv;
    }
    if (ph + 1 < PHn) {
        float2 n = pin[i + HW];
        float dx = n.x - pv.x, dy = n.y - pv.y;
        float inv = rsqrtf(dx*dx + dy*dy);
        gx -= ctr * dx * inv; gy -= ctr * dy * inv;
    }
    if (ph >= 1) {
        float2 n = pin[i - HW];
        float dx = pv.x - n.x, dy = pv.y - n.y;
        float inv = rsqrtf(dx*dx + dy*dy);
        gx += ctr * dx * inv; gy += ctr * dy * inv;
    }

    pout[i] = make_float2(pv.x - 0.5f*gx, pv.y - 0.5f*gy);
}

// FINAL node. Decoded harness geometry (DO NOT CHANGE):
//   output0 window floats [0, N): params.real
//   output1 window floats [N,2N): image_init.real
__global__ void k_writeout_all(float* __restrict__ out) {
    int i = blockIdx.x*blockDim.x + threadIdx.x;
    if (i >= Bn*HW) return;
    float2 p = g_p0[i];
    float2 v = g_init[i];
    out[i]          = p.x;
    out[i +   NPIX] = v.x;
    out[i + 2*NPIX] = p.y;
    out[i + 3*NPIX] = v.y;
}

// ---------------- host launcher --------------------------------------------
extern "C" void kernel_launch(void* const* d_in, const int* in_sizes, int n_in,
                              void* d_out, int out_size) {
    const float2* kd  = 0;
    const float2* kdc = 0;
    const float*  traj = 0;
    const float2* csm = 0;
    int n131 = 0;
    for (int i = 0; i < n_in; i++) {
        if (in_sizes[i] == 16384) {
            traj = (const float*)d_in[i];
        } else if (in_sizes[i] == 524288) {
            csm = (const float2*)d_in[i];
        } else if (in_sizes[i] == 131072) {
            if (n131 == 0) kd  = (const float2*)d_in[i];
            else           kdc = (const float2*)d_in[i];
            n131++;
        }
    }
    float* out = (float*)d_out;

    cudaFuncSetAttribute(k_adj, cudaFuncAttributeMaxDynamicSharedMemorySize, ADJ_SMEM);
    cudaFuncSetAttribute(k_fwd, cudaFuncAttributeMaxDynamicSharedMemorySize, FWD_SMEM);

    k_exp<<<Bn*Kn, Hn>>>(traj);
    k_csm<<<(Tn*CHn*HW + 255)/256, 256>>>(csm);

    k_adj<<<dim3(2, 2, BCn), 256, ADJ_SMEM>>>(kdc, 0);
    k_combine_init<<<(Bn*HW + 255)/256, 256>>>();

    for (int step = 0; step < 2; step++) {
        int psel = step & 1;
        k_fwd<<<dim3(Kn/128, 2, BCn), 256, FWD_SMEM>>>(psel);
        k_est2<<<(BCn*Kn + 255)/256, 256>>>(kd);
        k_adj<<<dim3(2, 2, BCn), 256, ADJ_SMEM>>>(nullptr, 1);
        k_update<<<(Bn*HW + 255)/256, 256>>>(psel);
    }

    k_writeout_all<<<(Bn*HW + 255)/256, 256>>>(out);
}